// round 1
// baseline (speedup 1.0000x reference)
#include <cuda_runtime.h>
#include <math.h>

// LTCAttentionCell fused kernel (round 0 baseline, fp32 SIMT).
//
// out[m,n] = (sigmoid(gate[m,n]) * tanh(dyn[m,n]) - h_ltc[m,n])
//            / (softplus(tau[m,n]) + softplus(cm[n]) + softplus(gleak[n]) + 1e-6)
// gate[m,n] = sum_k combined[m,k] * W_gd[n,     k] + b_gd[n]
// dyn [m,n] = sum_k combined[m,k] * W_gd[n+512, k] + b_gd[n+512]
// tau [m,n] = sum_k h_ltc[m,k]    * W_tau[n,    k] + b_tau[n]
// combined[m,:] = [x_t[m,0:128], h_ltc[m,0:512], context[m,0:256]]  (K=896)

#define B_ROWS 16384
#define IN_DIM 128
#define HID    512
#define ATT    256
#define KTOT   896   // IN_DIM + HID + ATT

#define BM 128
#define BN 64
#define BK 16
#define TM 8
#define TN 4
#define NTHREADS 256   // (BM/TM)*(BN/TN)

__device__ __forceinline__ float softplus_f(float x) {
    return (x > 20.0f) ? x : log1pf(expf(x));
}

__global__ void __launch_bounds__(NTHREADS)
ltc_fused_kernel(const float* __restrict__ h_ltc,
                 const float* __restrict__ x_t,
                 const float* __restrict__ context,
                 const float* __restrict__ W_gd,
                 const float* __restrict__ b_gd,
                 const float* __restrict__ W_tau,
                 const float* __restrict__ b_tau,
                 const float* __restrict__ gleak,
                 const float* __restrict__ cm,
                 float* __restrict__ out)
{
    __shared__ float As[BK][BM];   // A chunk, transposed: As[k][m]
    __shared__ float Bg[BK][BN];   // W_gd gate rows
    __shared__ float Bd[BK][BN];   // W_gd dynamics rows
    __shared__ float Bt[BK][BN];   // W_tau rows

    const int m0  = blockIdx.y * BM;
    const int n0  = blockIdx.x * BN;
    const int tid = threadIdx.x;

    // compute-tile coords
    const int trow = (tid >> 4) * TM;   // 0..120
    const int tcol = (tid & 15) * TN;   // 0..60

    // load coords: each thread loads float4s
    const int lk   = (tid & 3) * 4;     // k offset within BK chunk {0,4,8,12}
    const int lrow = tid >> 2;          // 0..63

    float acc_g[TM][TN];
    float acc_d[TM][TN];
    float acc_t[TM][TN];
    #pragma unroll
    for (int i = 0; i < TM; ++i)
        #pragma unroll
        for (int j = 0; j < TN; ++j) {
            acc_g[i][j] = 0.f; acc_d[i][j] = 0.f; acc_t[i][j] = 0.f;
        }

    for (int k0 = 0; k0 < KTOT; k0 += BK) {
        // ---- A chunk: combined[m0:m0+128, k0:k0+16].
        // Boundaries 128 and 640 are multiples of BK, so one source per chunk.
        const float* src; int scols; int scol0;
        if (k0 < IN_DIM)            { src = x_t;     scols = IN_DIM; scol0 = k0; }
        else if (k0 < IN_DIM + HID) { src = h_ltc;   scols = HID;    scol0 = k0 - IN_DIM; }
        else                        { src = context; scols = ATT;    scol0 = k0 - (IN_DIM + HID); }

        #pragma unroll
        for (int rr = 0; rr < 2; ++rr) {
            int m = lrow + rr * 64;
            float4 v = *reinterpret_cast<const float4*>(
                &src[(size_t)(m0 + m) * scols + scol0 + lk]);
            As[lk + 0][m] = v.x; As[lk + 1][m] = v.y;
            As[lk + 2][m] = v.z; As[lk + 3][m] = v.w;
        }

        const bool tau_active = (k0 >= IN_DIM) && (k0 < IN_DIM + HID);

        // ---- B chunks (weights): one float4 per thread per matrix
        {
            int n = lrow;   // 0..63
            float4 vg = *reinterpret_cast<const float4*>(
                &W_gd[(size_t)(n0 + n) * KTOT + k0 + lk]);
            Bg[lk + 0][n] = vg.x; Bg[lk + 1][n] = vg.y;
            Bg[lk + 2][n] = vg.z; Bg[lk + 3][n] = vg.w;

            float4 vd = *reinterpret_cast<const float4*>(
                &W_gd[(size_t)(n0 + n + HID) * KTOT + k0 + lk]);
            Bd[lk + 0][n] = vd.x; Bd[lk + 1][n] = vd.y;
            Bd[lk + 2][n] = vd.z; Bd[lk + 3][n] = vd.w;

            if (tau_active) {
                float4 vt = *reinterpret_cast<const float4*>(
                    &W_tau[(size_t)(n0 + n) * HID + (k0 - IN_DIM) + lk]);
                Bt[lk + 0][n] = vt.x; Bt[lk + 1][n] = vt.y;
                Bt[lk + 2][n] = vt.z; Bt[lk + 3][n] = vt.w;
            }
        }
        __syncthreads();

        if (tau_active) {
            #pragma unroll
            for (int kk = 0; kk < BK; ++kk) {
                float a[TM], bg[TN], bd[TN], bt[TN];
                #pragma unroll
                for (int i = 0; i < TM; ++i) a[i] = As[kk][trow + i];
                #pragma unroll
                for (int j = 0; j < TN; ++j) {
                    bg[j] = Bg[kk][tcol + j];
                    bd[j] = Bd[kk][tcol + j];
                    bt[j] = Bt[kk][tcol + j];
                }
                #pragma unroll
                for (int i = 0; i < TM; ++i)
                    #pragma unroll
                    for (int j = 0; j < TN; ++j) {
                        acc_g[i][j] = fmaf(a[i], bg[j], acc_g[i][j]);
                        acc_d[i][j] = fmaf(a[i], bd[j], acc_d[i][j]);
                        acc_t[i][j] = fmaf(a[i], bt[j], acc_t[i][j]);
                    }
            }
        } else {
            #pragma unroll
            for (int kk = 0; kk < BK; ++kk) {
                float a[TM], bg[TN], bd[TN];
                #pragma unroll
                for (int i = 0; i < TM; ++i) a[i] = As[kk][trow + i];
                #pragma unroll
                for (int j = 0; j < TN; ++j) {
                    bg[j] = Bg[kk][tcol + j];
                    bd[j] = Bd[kk][tcol + j];
                }
                #pragma unroll
                for (int i = 0; i < TM; ++i)
                    #pragma unroll
                    for (int j = 0; j < TN; ++j) {
                        acc_g[i][j] = fmaf(a[i], bg[j], acc_g[i][j]);
                        acc_d[i][j] = fmaf(a[i], bd[j], acc_d[i][j]);
                    }
            }
        }
        __syncthreads();
    }

    // ---- fused epilogue ----
    float bgate[TN], bdyn[TN], btau[TN], dconst[TN];
    #pragma unroll
    for (int j = 0; j < TN; ++j) {
        int n = n0 + tcol + j;
        bgate[j]  = b_gd[n];
        bdyn[j]   = b_gd[n + HID];
        btau[j]   = b_tau[n];
        dconst[j] = softplus_f(cm[n]) + softplus_f(gleak[n]) + 1e-6f;
    }

    #pragma unroll
    for (int i = 0; i < TM; ++i) {
        int m = m0 + trow + i;
        float4 res;
        float r[TN];
        #pragma unroll
        for (int j = 0; j < TN; ++j) {
            int n = n0 + tcol + j;
            float gate = acc_g[i][j] + bgate[j];
            float dyn  = acc_d[i][j] + bdyn[j];
            float tau  = softplus_f(acc_t[i][j] + btau[j]);
            float sig  = 1.0f / (1.0f + expf(-gate));
            float num  = sig * tanhf(dyn) - h_ltc[(size_t)m * HID + n];
            float den  = tau + dconst[j];
            r[j] = num / den;
        }
        res.x = r[0]; res.y = r[1]; res.z = r[2]; res.w = r[3];
        *reinterpret_cast<float4*>(&out[(size_t)m * HID + n0 + tcol]) = res;
    }
}

extern "C" void kernel_launch(void* const* d_in, const int* in_sizes, int n_in,
                              void* d_out, int out_size)
{
    // input order (setup_inputs): t, h_ltc, x_t, context, W_gd, b_gd,
    //                             W_tau, b_tau, gleak, cm
    const float* h_ltc   = (const float*)d_in[1];
    const float* x_t     = (const float*)d_in[2];
    const float* context = (const float*)d_in[3];
    const float* W_gd    = (const float*)d_in[4];
    const float* b_gd    = (const float*)d_in[5];
    const float* W_tau   = (const float*)d_in[6];
    const float* b_tau   = (const float*)d_in[7];
    const float* gleak   = (const float*)d_in[8];
    const float* cm      = (const float*)d_in[9];
    float* out = (float*)d_out;

    dim3 grid(HID / BN, B_ROWS / BM);   // (8, 128) = 1024 CTAs
    dim3 block(NTHREADS);
    ltc_fused_kernel<<<grid, block>>>(h_ltc, x_t, context, W_gd, b_gd,
                                      W_tau, b_tau, gleak, cm, out);
}

// round 2
// speedup vs baseline: 4.4994x; 4.4994x over previous
#include <cuda_runtime.h>
#include <cuda_bf16.h>
#include <math.h>
#include <stdint.h>

// LTCAttentionCell — round 2: bf16 split (3-term) tensor-core GEMM, fused epilogue.
//
// gate[m,n] = combined[m,:] . W_gd[n,:]       + b_gd[n]
// dyn [m,n] = combined[m,:] . W_gd[n+512,:]   + b_gd[n+512]
// tau [m,n] = h_ltc[m,:]    . W_tau[n,:]      + b_tau[n]
// out = (sigmoid(gate)*tanh(dyn) - h_ltc) / (softplus(tau)+softplus(cm)+softplus(gleak)+1e-6)

#define IN_DIM 128
#define HID    512
#define ATT    256
#define KTOT   896
#define BROWS  16384

#define BM 128
#define BN 64
#define BK 32
#define NCHUNKS (KTOT / BK)   // 28
#define NTHREADS 256

__device__ __forceinline__ float softplus_f(float x) {
    return (x > 20.0f) ? x : log1pf(expf(x));
}

// XOR-swizzled smem layout: rows of 32 bf16 (64B), 16B chunk c -> c ^ ((row>>1)&3).
// Conflict-free for ldmatrix row-groups of 8, zero padding. Element offset:
__device__ __forceinline__ int eoff(int row, int k) {
    return row * 32 + ((((k >> 3) ^ ((row >> 1) & 3)) << 3) | (k & 7));
}

__device__ __forceinline__ uint32_t s_u32(const void* p) {
    return (uint32_t)__cvta_generic_to_shared(p);
}

__device__ __forceinline__ void ldm_x4(uint32_t* d, uint32_t addr) {
    asm volatile("ldmatrix.sync.aligned.m8n8.x4.shared.b16 {%0,%1,%2,%3}, [%4];"
                 : "=r"(d[0]), "=r"(d[1]), "=r"(d[2]), "=r"(d[3]) : "r"(addr));
}

__device__ __forceinline__ void mma_bf16(float* c, const uint32_t* a, uint32_t b0, uint32_t b1) {
    asm volatile("mma.sync.aligned.m16n8k16.row.col.f32.bf16.bf16.f32 "
                 "{%0,%1,%2,%3}, {%4,%5,%6,%7}, {%8,%9}, {%0,%1,%2,%3};"
                 : "+f"(c[0]), "+f"(c[1]), "+f"(c[2]), "+f"(c[3])
                 : "r"(a[0]), "r"(a[1]), "r"(a[2]), "r"(a[3]), "r"(b0), "r"(b1));
}

// convert 4 fp32 -> bf16 hi + bf16 residual, store into both smem buffers
__device__ __forceinline__ void cvt_store(__nv_bfloat16* sh, __nv_bfloat16* sl,
                                          int row, int k, float4 v) {
    int e = eoff(row, k);
    float f[4] = {v.x, v.y, v.z, v.w};
    __nv_bfloat16 h[4], l[4];
#pragma unroll
    for (int i = 0; i < 4; ++i) {
        h[i] = __float2bfloat16(f[i]);
        l[i] = __float2bfloat16(f[i] - __bfloat162float(h[i]));
    }
    __nv_bfloat162 h01; h01.x = h[0]; h01.y = h[1];
    __nv_bfloat162 h23; h23.x = h[2]; h23.y = h[3];
    __nv_bfloat162 l01; l01.x = l[0]; l01.y = l[1];
    __nv_bfloat162 l23; l23.x = l[2]; l23.y = l[3];
    *reinterpret_cast<__nv_bfloat162*>(&sh[e])     = h01;
    *reinterpret_cast<__nv_bfloat162*>(&sh[e + 2]) = h23;
    *reinterpret_cast<__nv_bfloat162*>(&sl[e])     = l01;
    *reinterpret_cast<__nv_bfloat162*>(&sl[e + 2]) = l23;
}

// 24 MMAs for one output matrix at one k16 step: Ah*Bh + Al*Bh + Ah*Bl
__device__ __forceinline__ void do_mat(float acc[2][4][4],
                                       const __nv_bfloat16* Bh, const __nv_bfloat16* Bl,
                                       const uint32_t ah[2][4], const uint32_t al[2][4],
                                       int wn, int ks, int b_row, int b_k)
{
    uint32_t bh[2][4], bl[2][4];
#pragma unroll
    for (int half = 0; half < 2; ++half) {
        int row = wn + half * 16 + b_row;
        int kc  = ks + b_k;
        ldm_x4(bh[half], s_u32(&Bh[eoff(row, kc)]));
        ldm_x4(bl[half], s_u32(&Bl[eoff(row, kc)]));
    }
#pragma unroll
    for (int mb = 0; mb < 2; ++mb)
#pragma unroll
        for (int nb = 0; nb < 4; ++nb)
            mma_bf16(acc[mb][nb], ah[mb], bh[nb >> 1][(nb & 1) * 2], bh[nb >> 1][(nb & 1) * 2 + 1]);
#pragma unroll
    for (int mb = 0; mb < 2; ++mb)
#pragma unroll
        for (int nb = 0; nb < 4; ++nb)
            mma_bf16(acc[mb][nb], al[mb], bh[nb >> 1][(nb & 1) * 2], bh[nb >> 1][(nb & 1) * 2 + 1]);
#pragma unroll
    for (int mb = 0; mb < 2; ++mb)
#pragma unroll
        for (int nb = 0; nb < 4; ++nb)
            mma_bf16(acc[mb][nb], ah[mb], bl[nb >> 1][(nb & 1) * 2], bl[nb >> 1][(nb & 1) * 2 + 1]);
}

__global__ void __launch_bounds__(NTHREADS, 1)
ltc_mma_kernel(const float* __restrict__ h_ltc, const float* __restrict__ x_t,
               const float* __restrict__ context, const float* __restrict__ W_gd,
               const float* __restrict__ b_gd, const float* __restrict__ W_tau,
               const float* __restrict__ b_tau, const float* __restrict__ gleak,
               const float* __restrict__ cm, float* __restrict__ out)
{
    __shared__ __nv_bfloat16 sAh[BM * 32], sAl[BM * 32];
    __shared__ __nv_bfloat16 sBh[3][BN * 32], sBl[3][BN * 32];  // 0=gate 1=dyn 2=tau

    const int tid = threadIdx.x;
    const int m0 = blockIdx.y * BM;
    const int n0 = blockIdx.x * BN;

    // global->smem loader coords: 8 threads per row (float4 each), 32 rows/pass
    const int lrow = tid >> 3;        // 0..31
    const int lcol = (tid & 7) * 4;   // 0..28

    const int wid = tid >> 5, lane = tid & 31;
    const int wm = (wid & 3) * 32;    // warp m offset within CTA tile
    const int wn = (wid >> 2) * 32;   // warp n offset

    // ldmatrix per-thread addressing (x4, 4 8x8 matrices)
    const int a_row = ((lane >> 3) & 1) * 8 + (lane & 7);
    const int a_k   = ((lane >> 4) & 1) * 8;
    const int b_row = ((lane >> 4) & 1) * 8 + (lane & 7);
    const int b_k   = ((lane >> 3) & 1) * 8;

    float accg[2][4][4] = {}, accd[2][4][4] = {}, acct[2][4][4] = {};

    // register staging for software pipeline (10 float4 / thread)
    float4 ra[4], rg[2], rd[2], rt[2];

    auto load_stage = [&](int c) {
        int k0 = c * BK;
        const float* src; int scols, sc0;
        if (k0 < IN_DIM)            { src = x_t;     scols = IN_DIM; sc0 = k0; }
        else if (k0 < IN_DIM + HID) { src = h_ltc;   scols = HID;    sc0 = k0 - IN_DIM; }
        else                        { src = context; scols = ATT;    sc0 = k0 - IN_DIM - HID; }
#pragma unroll
        for (int p = 0; p < 4; ++p) {
            int row = p * 32 + lrow;
            ra[p] = *reinterpret_cast<const float4*>(&src[(size_t)(m0 + row) * scols + sc0 + lcol]);
        }
#pragma unroll
        for (int p = 0; p < 2; ++p) {
            int n = p * 32 + lrow;
            rg[p] = *reinterpret_cast<const float4*>(&W_gd[(size_t)(n0 + n) * KTOT + k0 + lcol]);
            rd[p] = *reinterpret_cast<const float4*>(&W_gd[(size_t)(n0 + n + HID) * KTOT + k0 + lcol]);
        }
        if (k0 >= IN_DIM && k0 < IN_DIM + HID) {
#pragma unroll
            for (int p = 0; p < 2; ++p) {
                int n = p * 32 + lrow;
                rt[p] = *reinterpret_cast<const float4*>(
                    &W_tau[(size_t)(n0 + n) * HID + (k0 - IN_DIM) + lcol]);
            }
        }
    };

    auto store_stage = [&](int c) {
#pragma unroll
        for (int p = 0; p < 4; ++p) cvt_store(sAh, sAl, p * 32 + lrow, lcol, ra[p]);
#pragma unroll
        for (int p = 0; p < 2; ++p) {
            cvt_store(sBh[0], sBl[0], p * 32 + lrow, lcol, rg[p]);
            cvt_store(sBh[1], sBl[1], p * 32 + lrow, lcol, rd[p]);
        }
        int k0 = c * BK;
        if (k0 >= IN_DIM && k0 < IN_DIM + HID) {
#pragma unroll
            for (int p = 0; p < 2; ++p)
                cvt_store(sBh[2], sBl[2], p * 32 + lrow, lcol, rt[p]);
        }
    };

    load_stage(0);

    for (int c = 0; c < NCHUNKS; ++c) {
        store_stage(c);
        __syncthreads();
        const bool tau_act = (c >= 4 && c < 20);   // k0 in [128, 640)
        if (c + 1 < NCHUNKS) load_stage(c + 1);    // prefetch next chunk (regs free after store)

#pragma unroll
        for (int ks = 0; ks < BK; ks += 16) {
            uint32_t ah[2][4], al[2][4];
#pragma unroll
            for (int mb = 0; mb < 2; ++mb) {
                int row = wm + mb * 16 + a_row;
                int kc  = ks + a_k;
                ldm_x4(ah[mb], s_u32(&sAh[eoff(row, kc)]));
                ldm_x4(al[mb], s_u32(&sAl[eoff(row, kc)]));
            }
            do_mat(accg, sBh[0], sBl[0], ah, al, wn, ks, b_row, b_k);
            do_mat(accd, sBh[1], sBl[1], ah, al, wn, ks, b_row, b_k);
            if (tau_act)
                do_mat(acct, sBh[2], sBl[2], ah, al, wn, ks, b_row, b_k);
        }
        __syncthreads();
    }

    // ---- fused epilogue ----
    const int g  = lane >> 2;
    const int c2 = (lane & 3) * 2;
#pragma unroll
    for (int mb = 0; mb < 2; ++mb)
#pragma unroll
        for (int nb = 0; nb < 4; ++nb) {
            const int n = n0 + wn + nb * 8 + c2;
            const float bg0 = __ldg(&b_gd[n]),        bg1 = __ldg(&b_gd[n + 1]);
            const float bd0 = __ldg(&b_gd[n + HID]),  bd1 = __ldg(&b_gd[n + HID + 1]);
            const float bt0 = __ldg(&b_tau[n]),       bt1 = __ldg(&b_tau[n + 1]);
            const float dc0 = softplus_f(__ldg(&cm[n]))   + softplus_f(__ldg(&gleak[n]))   + 1e-6f;
            const float dc1 = softplus_f(__ldg(&cm[n+1])) + softplus_f(__ldg(&gleak[n+1])) + 1e-6f;
#pragma unroll
            for (int h = 0; h < 2; ++h) {
                const int m = m0 + wm + mb * 16 + h * 8 + g;
                const float hl0 = __ldg(&h_ltc[(size_t)m * HID + n]);
                const float hl1 = __ldg(&h_ltc[(size_t)m * HID + n + 1]);

                float gate0 = accg[mb][nb][h * 2 + 0] + bg0;
                float gate1 = accg[mb][nb][h * 2 + 1] + bg1;
                float dyn0  = accd[mb][nb][h * 2 + 0] + bd0;
                float dyn1  = accd[mb][nb][h * 2 + 1] + bd1;
                float tau0  = softplus_f(acct[mb][nb][h * 2 + 0] + bt0);
                float tau1  = softplus_f(acct[mb][nb][h * 2 + 1] + bt1);

                float sig0 = 1.0f / (1.0f + expf(-gate0));
                float sig1 = 1.0f / (1.0f + expf(-gate1));
                float r0 = (sig0 * tanhf(dyn0) - hl0) / (tau0 + dc0);
                float r1 = (sig1 * tanhf(dyn1) - hl1) / (tau1 + dc1);

                float2 o; o.x = r0; o.y = r1;
                *reinterpret_cast<float2*>(&out[(size_t)m * HID + n]) = o;
            }
        }
}

extern "C" void kernel_launch(void* const* d_in, const int* in_sizes, int n_in,
                              void* d_out, int out_size)
{
    // input order: t, h_ltc, x_t, context, W_gd, b_gd, W_tau, b_tau, gleak, cm
    const float* h_ltc   = (const float*)d_in[1];
    const float* x_t     = (const float*)d_in[2];
    const float* context = (const float*)d_in[3];
    const float* W_gd    = (const float*)d_in[4];
    const float* b_gd    = (const float*)d_in[5];
    const float* W_tau   = (const float*)d_in[6];
    const float* b_tau   = (const float*)d_in[7];
    const float* gleak   = (const float*)d_in[8];
    const float* cm      = (const float*)d_in[9];
    float* out = (float*)d_out;

    dim3 grid(HID / BN, BROWS / BM);   // (8, 128)
    dim3 block(NTHREADS);
    ltc_mma_kernel<<<grid, block>>>(h_ltc, x_t, context, W_gd, b_gd,
                                    W_tau, b_tau, gleak, cm, out);
}

// round 4
// speedup vs baseline: 6.3339x; 1.4077x over previous
#include <cuda_runtime.h>
#include <cuda_fp16.h>
#include <math.h>
#include <stdint.h>

// LTCAttentionCell — round 4: fp16 2-term split (A=Ah+Al fp16, B fp16),
// mma.sync.m16n8k16 tensor cores, pre-split scratch, cp.async 3-stage pipeline.
// (tcgen05 is unavailable: harness ptxas targets sm_103 without the 'a' feature.)

#define IN_DIM 128
#define HID    512
#define ATT    256
#define KTOT   896
#define BROWS  16384

#define BM 128
#define BN 64
#define KBLK 32
#define NCH (KTOT / KBLK)        // 28
#define NTH 256
#define STAGES 3
// stage: A 128x128B (hi|lo k32) = 16K, Bg/Bd/Bt 64x64B = 4K each
#define STAGE_BYTES (16384 + 3 * 4096)
#define SMEM_DYN (STAGES * STAGE_BYTES + 128)

// ---------------- packed fp16 scratch ----------------
__device__ __half g_comb[(size_t)BROWS * 1792];   // [16384][28 * [hi32|lo32]]
__device__ __half g_wgd [(size_t)1024  * 896];    // fp16, row-major
__device__ __half g_wtau[(size_t)512   * 512];    // fp16, row-major

__device__ __forceinline__ uint32_t s2u(const void* p) {
    return (uint32_t)__cvta_generic_to_shared(p);
}
__device__ __forceinline__ void cp16(uint32_t dst, const void* src) {
    asm volatile("cp.async.cg.shared.global [%0], [%1], 16;" :: "r"(dst), "l"(src));
}
__device__ __forceinline__ void cp_commit() {
    asm volatile("cp.async.commit_group;" ::: "memory");
}
template<int N> __device__ __forceinline__ void cp_wait() {
    asm volatile("cp.async.wait_group %0;" :: "n"(N) : "memory");
}
__device__ __forceinline__ void ldm_x4(uint32_t* d, uint32_t addr) {
    asm volatile("ldmatrix.sync.aligned.m8n8.x4.shared.b16 {%0,%1,%2,%3}, [%4];"
                 : "=r"(d[0]), "=r"(d[1]), "=r"(d[2]), "=r"(d[3]) : "r"(addr));
}
__device__ __forceinline__ void mma_f16(float* c, const uint32_t* a, uint32_t b0, uint32_t b1) {
    asm volatile("mma.sync.aligned.m16n8k16.row.col.f32.f16.f16.f32 "
                 "{%0,%1,%2,%3}, {%4,%5,%6,%7}, {%8,%9}, {%0,%1,%2,%3};"
                 : "+f"(c[0]), "+f"(c[1]), "+f"(c[2]), "+f"(c[3])
                 : "r"(a[0]), "r"(a[1]), "r"(a[2]), "r"(a[3]), "r"(b0), "r"(b1));
}
__device__ __forceinline__ float softplus_f(float x) {
    return (x > 20.0f) ? x : log1pf(expf(x));
}

// smem addressing
// A rows: 128B = 8x16B chunks [hi k0..31 | lo k0..31], chunk swizzle c ^ (row&7)
__device__ __forceinline__ uint32_t addrA(uint32_t base, int row, int k, int lo) {
    int c = (k >> 3) | (lo << 2);
    return base + row * 128 + (((c ^ (row & 7)) << 4) | ((k & 7) * 2));
}
// B rows: 64B = 4x16B chunks (k32), chunk swizzle c ^ ((row>>1)&3)
__device__ __forceinline__ uint32_t addrB(uint32_t base, int row, int k) {
    int c = k >> 3;
    return base + row * 64 + (((c ^ ((row >> 1) & 3)) << 4) | ((k & 7) * 2));
}

// ---------------- pre-pass kernels ----------------
__global__ void __launch_bounds__(256)
prep_combined(const float* __restrict__ h_ltc, const float* __restrict__ x_t,
              const float* __restrict__ context)
{
    int idx = blockIdx.x * 256 + threadIdx.x;   // 16384*224
    int m = idx / 224;
    int q = idx - m * 224;
    int b = q >> 3;
    int j = (q & 7) * 4;
    int col = b * 32 + j;
    const float* src;
    if (col < IN_DIM)            src = x_t     + (size_t)m * IN_DIM + col;
    else if (col < IN_DIM + HID) src = h_ltc   + (size_t)m * HID    + (col - IN_DIM);
    else                         src = context + (size_t)m * ATT    + (col - IN_DIM - HID);
    float4 v = *reinterpret_cast<const float4*>(src);
    float f[4] = {v.x, v.y, v.z, v.w};
    __half h[4], l[4];
#pragma unroll
    for (int i = 0; i < 4; ++i) {
        h[i] = __float2half_rn(f[i]);
        l[i] = __float2half_rn(f[i] - __half2float(h[i]));
    }
    __half* dst = &g_comb[(size_t)m * 1792 + b * 64 + j];
    __half2 p;
    p.x = h[0]; p.y = h[1]; *reinterpret_cast<__half2*>(dst + 0)  = p;
    p.x = h[2]; p.y = h[3]; *reinterpret_cast<__half2*>(dst + 2)  = p;
    p.x = l[0]; p.y = l[1]; *reinterpret_cast<__half2*>(dst + 32) = p;
    p.x = l[2]; p.y = l[3]; *reinterpret_cast<__half2*>(dst + 34) = p;
}

__global__ void __launch_bounds__(256)
prep_weights(const float* __restrict__ W_gd, const float* __restrict__ W_tau)
{
    int idx = blockIdx.x * 256 + threadIdx.x;   // 229376 + 65536
    const float* src;
    __half* dst;
    if (idx < 229376) {
        int row = idx / 224;
        int j = (idx - row * 224) * 4;
        src = &W_gd[(size_t)row * KTOT + j];
        dst = &g_wgd[(size_t)row * KTOT + j];
    } else {
        int e = idx - 229376;
        int row = e >> 7;
        int j = (e & 127) * 4;
        src = &W_tau[(size_t)row * HID + j];
        dst = &g_wtau[(size_t)row * HID + j];
    }
    float4 v = *reinterpret_cast<const float4*>(src);
    __half2 p0, p1;
    p0.x = __float2half_rn(v.x); p0.y = __float2half_rn(v.y);
    p1.x = __float2half_rn(v.z); p1.y = __float2half_rn(v.w);
    *reinterpret_cast<__half2*>(dst + 0) = p0;
    *reinterpret_cast<__half2*>(dst + 2) = p1;
}

// ---------------- main kernel ----------------
__global__ void __launch_bounds__(NTH, 1)
ltc_mma16_kernel(const float* __restrict__ h_ltc, const float* __restrict__ b_gd,
                 const float* __restrict__ b_tau, const float* __restrict__ gleak,
                 const float* __restrict__ cm, float* __restrict__ out)
{
    extern __shared__ char smem[];
    const uint32_t data = (s2u(smem) + 127) & ~127u;

    const int tid  = threadIdx.x;
    const int wid  = tid >> 5;
    const int lane = tid & 31;
    const int m0 = blockIdx.y * BM;
    const int n0 = blockIdx.x * BN;

    const int wm = (wid & 3) * 32;
    const int wn = (wid >> 2) * 32;
    const int a_row = ((lane >> 3) & 1) * 8 + (lane & 7);
    const int a_k   = ((lane >> 4) & 1) * 8;
    const int b_row = ((lane >> 4) & 1) * 8 + (lane & 7);
    const int b_k   = ((lane >> 3) & 1) * 8;

    float accg[2][4][4] = {}, accd[2][4][4] = {}, acct[2][4][4] = {};

    // loader thread coords
    const int ar = tid >> 3, ach = tid & 7;          // A: 4 iters of (32 rows x 8 ch)
    const int br = tid >> 2, bch = tid & 3;          // B: 64 rows x 4 ch

    auto load_chunk = [&](int c) {
        uint32_t st = data + (c % STAGES) * STAGE_BYTES;
        const __half* pa = g_comb + (size_t)m0 * 1792 + c * 64;
#pragma unroll
        for (int i = 0; i < 4; ++i) {
            int r = ar + i * 32;
            cp16(st + r * 128 + ((ach ^ (r & 7)) << 4),
                 pa + (size_t)r * 1792 + ach * 8);
        }
        uint32_t boff = br * 64 + (((bch ^ ((br >> 1) & 3)) << 4));
        const __half* pg = g_wgd + (size_t)(n0 + br) * KTOT + c * 32 + bch * 8;
        cp16(st + 16384 + boff, pg);
        cp16(st + 20480 + boff, pg + (size_t)HID * KTOT);
        if (c >= 4 && c < 20) {
            cp16(st + 24576 + boff,
                 g_wtau + (size_t)(n0 + br) * HID + (c - 4) * 32 + bch * 8);
        }
        cp_commit();
    };

    load_chunk(0); load_chunk(1); load_chunk(2);

    for (int c = 0; c < NCH; ++c) {
        int rem = NCH - 1 - c;
        if (rem >= 2)      cp_wait<2>();
        else if (rem == 1) cp_wait<1>();
        else               cp_wait<0>();
        __syncthreads();

        const uint32_t st = data + (c % STAGES) * STAGE_BYTES;
        const bool tau_act = (c >= 4 && c < 20);

#pragma unroll
        for (int ks = 0; ks < KBLK; ks += 16) {
            uint32_t ah[2][4], al[2][4];
#pragma unroll
            for (int mb = 0; mb < 2; ++mb) {
                int row = wm + mb * 16 + a_row;
                ldm_x4(ah[mb], addrA(st, row, ks + a_k, 0));
                ldm_x4(al[mb], addrA(st, row, ks + a_k, 1));
            }
            // gate
            {
                uint32_t b[2][4];
#pragma unroll
                for (int h = 0; h < 2; ++h)
                    ldm_x4(b[h], addrB(st + 16384, wn + h * 16 + b_row, ks + b_k));
#pragma unroll
                for (int mb = 0; mb < 2; ++mb)
#pragma unroll
                    for (int nb = 0; nb < 4; ++nb)
                        mma_f16(accg[mb][nb], ah[mb], b[nb >> 1][(nb & 1) * 2], b[nb >> 1][(nb & 1) * 2 + 1]);
#pragma unroll
                for (int mb = 0; mb < 2; ++mb)
#pragma unroll
                    for (int nb = 0; nb < 4; ++nb)
                        mma_f16(accg[mb][nb], al[mb], b[nb >> 1][(nb & 1) * 2], b[nb >> 1][(nb & 1) * 2 + 1]);
            }
            // dyn
            {
                uint32_t b[2][4];
#pragma unroll
                for (int h = 0; h < 2; ++h)
                    ldm_x4(b[h], addrB(st + 20480, wn + h * 16 + b_row, ks + b_k));
#pragma unroll
                for (int mb = 0; mb < 2; ++mb)
#pragma unroll
                    for (int nb = 0; nb < 4; ++nb)
                        mma_f16(accd[mb][nb], ah[mb], b[nb >> 1][(nb & 1) * 2], b[nb >> 1][(nb & 1) * 2 + 1]);
#pragma unroll
                for (int mb = 0; mb < 2; ++mb)
#pragma unroll
                    for (int nb = 0; nb < 4; ++nb)
                        mma_f16(accd[mb][nb], al[mb], b[nb >> 1][(nb & 1) * 2], b[nb >> 1][(nb & 1) * 2 + 1]);
            }
            // tau
            if (tau_act) {
                uint32_t b[2][4];
#pragma unroll
                for (int h = 0; h < 2; ++h)
                    ldm_x4(b[h], addrB(st + 24576, wn + h * 16 + b_row, ks + b_k));
#pragma unroll
                for (int mb = 0; mb < 2; ++mb)
#pragma unroll
                    for (int nb = 0; nb < 4; ++nb)
                        mma_f16(acct[mb][nb], ah[mb], b[nb >> 1][(nb & 1) * 2], b[nb >> 1][(nb & 1) * 2 + 1]);
#pragma unroll
                for (int mb = 0; mb < 2; ++mb)
#pragma unroll
                    for (int nb = 0; nb < 4; ++nb)
                        mma_f16(acct[mb][nb], al[mb], b[nb >> 1][(nb & 1) * 2], b[nb >> 1][(nb & 1) * 2 + 1]);
            }
        }
        __syncthreads();
        if (c + STAGES < NCH) load_chunk(c + STAGES);
    }

    // ---- fused epilogue ----
    const int g  = lane >> 2;
    const int c2 = (lane & 3) * 2;
#pragma unroll
    for (int mb = 0; mb < 2; ++mb)
#pragma unroll
        for (int nb = 0; nb < 4; ++nb) {
            const int n = n0 + wn + nb * 8 + c2;
            const float bg0 = __ldg(&b_gd[n]),        bg1 = __ldg(&b_gd[n + 1]);
            const float bd0 = __ldg(&b_gd[n + HID]),  bd1 = __ldg(&b_gd[n + HID + 1]);
            const float bt0 = __ldg(&b_tau[n]),       bt1 = __ldg(&b_tau[n + 1]);
            const float dc0 = softplus_f(__ldg(&cm[n]))   + softplus_f(__ldg(&gleak[n]))   + 1e-6f;
            const float dc1 = softplus_f(__ldg(&cm[n+1])) + softplus_f(__ldg(&gleak[n+1])) + 1e-6f;
#pragma unroll
            for (int h = 0; h < 2; ++h) {
                const int m = m0 + wm + mb * 16 + h * 8 + g;
                const float hl0 = __ldg(&h_ltc[(size_t)m * HID + n]);
                const float hl1 = __ldg(&h_ltc[(size_t)m * HID + n + 1]);

                float gate0 = accg[mb][nb][h * 2 + 0] + bg0;
                float gate1 = accg[mb][nb][h * 2 + 1] + bg1;
                float dyn0  = accd[mb][nb][h * 2 + 0] + bd0;
                float dyn1  = accd[mb][nb][h * 2 + 1] + bd1;
                float tau0  = softplus_f(acct[mb][nb][h * 2 + 0] + bt0);
                float tau1  = softplus_f(acct[mb][nb][h * 2 + 1] + bt1);

                float sig0 = 1.0f / (1.0f + expf(-gate0));
                float sig1 = 1.0f / (1.0f + expf(-gate1));
                float r0 = (sig0 * tanhf(dyn0) - hl0) / (tau0 + dc0);
                float r1 = (sig1 * tanhf(dyn1) - hl1) / (tau1 + dc1);

                float2 o; o.x = r0; o.y = r1;
                *reinterpret_cast<float2*>(&out[(size_t)m * HID + n]) = o;
            }
        }
}

extern "C" void kernel_launch(void* const* d_in, const int* in_sizes, int n_in,
                              void* d_out, int out_size)
{
    // input order: t, h_ltc, x_t, context, W_gd, b_gd, W_tau, b_tau, gleak, cm
    const float* h_ltc   = (const float*)d_in[1];
    const float* x_t     = (const float*)d_in[2];
    const float* context = (const float*)d_in[3];
    const float* W_gd    = (const float*)d_in[4];
    const float* b_gd    = (const float*)d_in[5];
    const float* W_tau   = (const float*)d_in[6];
    const float* b_tau   = (const float*)d_in[7];
    const float* gleak   = (const float*)d_in[8];
    const float* cm      = (const float*)d_in[9];
    float* out = (float*)d_out;

    static int configured = 0;
    cudaFuncSetAttribute(ltc_mma16_kernel,
                         cudaFuncAttributeMaxDynamicSharedMemorySize, SMEM_DYN);
    (void)configured;

    prep_combined<<<14336, 256>>>(h_ltc, x_t, context);
    prep_weights<<<1152, 256>>>(W_gd, W_tau);

    dim3 grid(HID / BN, BROWS / BM);   // (8, 128)
    ltc_mma16_kernel<<<grid, NTH, SMEM_DYN>>>(h_ltc, b_gd, b_tau, gleak, cm, out);
}

// round 5
// speedup vs baseline: 6.4332x; 1.0157x over previous
#include <cuda_runtime.h>
#include <cuda_fp16.h>
#include <math.h>
#include <stdint.h>

// LTCAttentionCell — round 5: same fp16 2-term split + cp.async pipeline as R4,
// but 512 threads (16 warps, 4/SMSP), warp tile 32x16 to cut regs and double
// scheduler-level parallelism. tcgen05 unavailable (ptxas targets sm_103).

#define IN_DIM 128
#define HID    512
#define ATT    256
#define KTOT   896
#define BROWS  16384

#define BM 128
#define BN 64
#define KBLK 32
#define NCH (KTOT / KBLK)        // 28
#define NTH 512
#define STAGES 3
// stage: A 128x128B (hi|lo k32) = 16K, Bg/Bd/Bt 64x64B = 4K each
#define STAGE_BYTES (16384 + 3 * 4096)
#define SMEM_DYN (STAGES * STAGE_BYTES + 128)

// ---------------- packed fp16 scratch ----------------
__device__ __half g_comb[(size_t)BROWS * 1792];   // [16384][28 * [hi32|lo32]]
__device__ __half g_wgd [(size_t)1024  * 896];
__device__ __half g_wtau[(size_t)512   * 512];

__device__ __forceinline__ uint32_t s2u(const void* p) {
    return (uint32_t)__cvta_generic_to_shared(p);
}
__device__ __forceinline__ void cp16(uint32_t dst, const void* src) {
    asm volatile("cp.async.cg.shared.global [%0], [%1], 16;" :: "r"(dst), "l"(src));
}
__device__ __forceinline__ void cp_commit() {
    asm volatile("cp.async.commit_group;" ::: "memory");
}
template<int N> __device__ __forceinline__ void cp_wait() {
    asm volatile("cp.async.wait_group %0;" :: "n"(N) : "memory");
}
__device__ __forceinline__ void ldm_x4(uint32_t* d, uint32_t addr) {
    asm volatile("ldmatrix.sync.aligned.m8n8.x4.shared.b16 {%0,%1,%2,%3}, [%4];"
                 : "=r"(d[0]), "=r"(d[1]), "=r"(d[2]), "=r"(d[3]) : "r"(addr));
}
__device__ __forceinline__ void mma_f16(float* c, const uint32_t* a, uint32_t b0, uint32_t b1) {
    asm volatile("mma.sync.aligned.m16n8k16.row.col.f32.f16.f16.f32 "
                 "{%0,%1,%2,%3}, {%4,%5,%6,%7}, {%8,%9}, {%0,%1,%2,%3};"
                 : "+f"(c[0]), "+f"(c[1]), "+f"(c[2]), "+f"(c[3])
                 : "r"(a[0]), "r"(a[1]), "r"(a[2]), "r"(a[3]), "r"(b0), "r"(b1));
}
__device__ __forceinline__ float softplus_f(float x) {
    return (x > 20.0f) ? x : log1pf(expf(x));
}

// A rows: 128B = 8x16B chunks [hi k0..31 | lo k0..31], chunk swizzle c ^ (row&7)
__device__ __forceinline__ uint32_t addrA(uint32_t base, int row, int k, int lo) {
    int c = (k >> 3) | (lo << 2);
    return base + row * 128 + (((c ^ (row & 7)) << 4) | ((k & 7) * 2));
}
// B rows: 64B = 4x16B chunks (k32), chunk swizzle c ^ ((row>>1)&3)
__device__ __forceinline__ uint32_t addrB(uint32_t base, int row, int k) {
    int c = k >> 3;
    return base + row * 64 + (((c ^ ((row >> 1) & 3)) << 4) | ((k & 7) * 2));
}

// ---------------- pre-pass kernels ----------------
__global__ void __launch_bounds__(256)
prep_combined(const float* __restrict__ h_ltc, const float* __restrict__ x_t,
              const float* __restrict__ context)
{
    int idx = blockIdx.x * 256 + threadIdx.x;   // 16384*224
    int m = idx / 224;
    int q = idx - m * 224;
    int b = q >> 3;
    int j = (q & 7) * 4;
    int col = b * 32 + j;
    const float* src;
    if (col < IN_DIM)            src = x_t     + (size_t)m * IN_DIM + col;
    else if (col < IN_DIM + HID) src = h_ltc   + (size_t)m * HID    + (col - IN_DIM);
    else                         src = context + (size_t)m * ATT    + (col - IN_DIM - HID);
    float4 v = *reinterpret_cast<const float4*>(src);
    float f[4] = {v.x, v.y, v.z, v.w};
    __half h[4], l[4];
#pragma unroll
    for (int i = 0; i < 4; ++i) {
        h[i] = __float2half_rn(f[i]);
        l[i] = __float2half_rn(f[i] - __half2float(h[i]));
    }
    __half* dst = &g_comb[(size_t)m * 1792 + b * 64 + j];
    __half2 p;
    p.x = h[0]; p.y = h[1]; *reinterpret_cast<__half2*>(dst + 0)  = p;
    p.x = h[2]; p.y = h[3]; *reinterpret_cast<__half2*>(dst + 2)  = p;
    p.x = l[0]; p.y = l[1]; *reinterpret_cast<__half2*>(dst + 32) = p;
    p.x = l[2]; p.y = l[3]; *reinterpret_cast<__half2*>(dst + 34) = p;
}

__global__ void __launch_bounds__(256)
prep_weights(const float* __restrict__ W_gd, const float* __restrict__ W_tau)
{
    int idx = blockIdx.x * 256 + threadIdx.x;   // 229376 + 65536
    const float* src;
    __half* dst;
    if (idx < 229376) {
        int row = idx / 224;
        int j = (idx - row * 224) * 4;
        src = &W_gd[(size_t)row * KTOT + j];
        dst = &g_wgd[(size_t)row * KTOT + j];
    } else {
        int e = idx - 229376;
        int row = e >> 7;
        int j = (e & 127) * 4;
        src = &W_tau[(size_t)row * HID + j];
        dst = &g_wtau[(size_t)row * HID + j];
    }
    float4 v = *reinterpret_cast<const float4*>(src);
    __half2 p0, p1;
    p0.x = __float2half_rn(v.x); p0.y = __float2half_rn(v.y);
    p1.x = __float2half_rn(v.z); p1.y = __float2half_rn(v.w);
    *reinterpret_cast<__half2*>(dst + 0) = p0;
    *reinterpret_cast<__half2*>(dst + 2) = p1;
}

// ---------------- main kernel ----------------
__global__ void __launch_bounds__(NTH, 1)
ltc_mma16_kernel(const float* __restrict__ h_ltc, const float* __restrict__ b_gd,
                 const float* __restrict__ b_tau, const float* __restrict__ gleak,
                 const float* __restrict__ cm, float* __restrict__ out)
{
    extern __shared__ char smem[];
    const uint32_t data = (s2u(smem) + 127) & ~127u;

    const int tid  = threadIdx.x;
    const int wid  = tid >> 5;
    const int lane = tid & 31;
    const int m0 = blockIdx.y * BM;
    const int n0 = blockIdx.x * BN;

    // 16 warps: 4 m-warps x 4 n-warps; warp tile 32m x 16n
    const int wm = (wid & 3) * 32;
    const int wn = (wid >> 2) * 16;
    const int a_row = ((lane >> 3) & 1) * 8 + (lane & 7);
    const int a_k   = ((lane >> 4) & 1) * 8;
    const int b_row = ((lane >> 4) & 1) * 8 + (lane & 7);
    const int b_k   = ((lane >> 3) & 1) * 8;

    float accg[2][2][4] = {}, accd[2][2][4] = {}, acct[2][2][4] = {};

    // loader coords: A: 512 threads, 2 rows each (128 rows x 8 chunks)
    const int ar = tid >> 3, ach = tid & 7;         // ar 0..63, rows ar and ar+64
    // B: slot s = tid & 255 -> row s>>2, chunk s&3
    const int br = (tid & 255) >> 2, bch = tid & 3;
    const bool lowhalf = tid < 256;

    auto load_chunk = [&](int c) {
        uint32_t st = data + (c % STAGES) * STAGE_BYTES;
        const __half* pa = g_comb + (size_t)m0 * 1792 + c * 64;
#pragma unroll
        for (int i = 0; i < 2; ++i) {
            int r = ar + i * 64;
            cp16(st + r * 128 + ((ach ^ (r & 7)) << 4),
                 pa + (size_t)r * 1792 + ach * 8);
        }
        uint32_t boff = br * 64 + (((bch ^ ((br >> 1) & 3)) << 4));
        if (lowhalf) {
            cp16(st + 16384 + boff,
                 g_wgd + (size_t)(n0 + br) * KTOT + c * 32 + bch * 8);
            if (c >= 4 && c < 20)
                cp16(st + 24576 + boff,
                     g_wtau + (size_t)(n0 + br) * HID + (c - 4) * 32 + bch * 8);
        } else {
            cp16(st + 20480 + boff,
                 g_wgd + (size_t)(HID + n0 + br) * KTOT + c * 32 + bch * 8);
        }
        cp_commit();
    };

    load_chunk(0); load_chunk(1); load_chunk(2);

    for (int c = 0; c < NCH; ++c) {
        int rem = NCH - 1 - c;
        if (rem >= 2)      cp_wait<2>();
        else if (rem == 1) cp_wait<1>();
        else               cp_wait<0>();
        __syncthreads();

        const uint32_t st = data + (c % STAGES) * STAGE_BYTES;
        const bool tau_act = (c >= 4 && c < 20);

#pragma unroll
        for (int ks = 0; ks < KBLK; ks += 16) {
            uint32_t ah[2][4], al[2][4];
#pragma unroll
            for (int mb = 0; mb < 2; ++mb) {
                int row = wm + mb * 16 + a_row;
                ldm_x4(ah[mb], addrA(st, row, ks + a_k, 0));
                ldm_x4(al[mb], addrA(st, row, ks + a_k, 1));
            }
            uint32_t bg[4], bd[4], bt[4];
            ldm_x4(bg, addrB(st + 16384, wn + b_row, ks + b_k));
            ldm_x4(bd, addrB(st + 20480, wn + b_row, ks + b_k));
            if (tau_act)
                ldm_x4(bt, addrB(st + 24576, wn + b_row, ks + b_k));

#pragma unroll
            for (int mb = 0; mb < 2; ++mb)
#pragma unroll
                for (int nb = 0; nb < 2; ++nb) {
                    mma_f16(accg[mb][nb], ah[mb], bg[nb * 2], bg[nb * 2 + 1]);
                    mma_f16(accd[mb][nb], ah[mb], bd[nb * 2], bd[nb * 2 + 1]);
                }
#pragma unroll
            for (int mb = 0; mb < 2; ++mb)
#pragma unroll
                for (int nb = 0; nb < 2; ++nb) {
                    mma_f16(accg[mb][nb], al[mb], bg[nb * 2], bg[nb * 2 + 1]);
                    mma_f16(accd[mb][nb], al[mb], bd[nb * 2], bd[nb * 2 + 1]);
                }
            if (tau_act) {
#pragma unroll
                for (int mb = 0; mb < 2; ++mb)
#pragma unroll
                    for (int nb = 0; nb < 2; ++nb) {
                        mma_f16(acct[mb][nb], ah[mb], bt[nb * 2], bt[nb * 2 + 1]);
                        mma_f16(acct[mb][nb], al[mb], bt[nb * 2], bt[nb * 2 + 1]);
                    }
            }
        }
        __syncthreads();
        if (c + STAGES < NCH) load_chunk(c + STAGES);
    }

    // ---- fused epilogue (warp tile 32x16) ----
    const int g  = lane >> 2;
    const int c2 = (lane & 3) * 2;
#pragma unroll
    for (int mb = 0; mb < 2; ++mb)
#pragma unroll
        for (int nb = 0; nb < 2; ++nb) {
            const int n = n0 + wn + nb * 8 + c2;
            const float bg0 = __ldg(&b_gd[n]),        bg1 = __ldg(&b_gd[n + 1]);
            const float bd0 = __ldg(&b_gd[n + HID]),  bd1 = __ldg(&b_gd[n + HID + 1]);
            const float bt0 = __ldg(&b_tau[n]),       bt1 = __ldg(&b_tau[n + 1]);
            const float dc0 = softplus_f(__ldg(&cm[n]))   + softplus_f(__ldg(&gleak[n]))   + 1e-6f;
            const float dc1 = softplus_f(__ldg(&cm[n+1])) + softplus_f(__ldg(&gleak[n+1])) + 1e-6f;
#pragma unroll
            for (int h = 0; h < 2; ++h) {
                const int m = m0 + wm + mb * 16 + h * 8 + g;
                const float hl0 = __ldg(&h_ltc[(size_t)m * HID + n]);
                const float hl1 = __ldg(&h_ltc[(size_t)m * HID + n + 1]);

                float gate0 = accg[mb][nb][h * 2 + 0] + bg0;
                float gate1 = accg[mb][nb][h * 2 + 1] + bg1;
                float dyn0  = accd[mb][nb][h * 2 + 0] + bd0;
                float dyn1  = accd[mb][nb][h * 2 + 1] + bd1;
                float tau0  = softplus_f(acct[mb][nb][h * 2 + 0] + bt0);
                float tau1  = softplus_f(acct[mb][nb][h * 2 + 1] + bt1);

                float sig0 = 1.0f / (1.0f + expf(-gate0));
                float sig1 = 1.0f / (1.0f + expf(-gate1));
                float r0 = (sig0 * tanhf(dyn0) - hl0) / (tau0 + dc0);
                float r1 = (sig1 * tanhf(dyn1) - hl1) / (tau1 + dc1);

                float2 o; o.x = r0; o.y = r1;
                *reinterpret_cast<float2*>(&out[(size_t)m * HID + n]) = o;
            }
        }
}

extern "C" void kernel_launch(void* const* d_in, const int* in_sizes, int n_in,
                              void* d_out, int out_size)
{
    // input order: t, h_ltc, x_t, context, W_gd, b_gd, W_tau, b_tau, gleak, cm
    const float* h_ltc   = (const float*)d_in[1];
    const float* x_t     = (const float*)d_in[2];
    const float* context = (const float*)d_in[3];
    const float* W_gd    = (const float*)d_in[4];
    const float* b_gd    = (const float*)d_in[5];
    const float* W_tau   = (const float*)d_in[6];
    const float* b_tau   = (const float*)d_in[7];
    const float* gleak   = (const float*)d_in[8];
    const float* cm      = (const float*)d_in[9];
    float* out = (float*)d_out;

    cudaFuncSetAttribute(ltc_mma16_kernel,
                         cudaFuncAttributeMaxDynamicSharedMemorySize, SMEM_DYN);

    prep_combined<<<14336, 256>>>(h_ltc, x_t, context);
    prep_weights<<<1152, 256>>>(W_gd, W_tau);

    dim3 grid(HID / BN, BROWS / BM);   // (8, 128)
    ltc_mma16_kernel<<<grid, NTH, SMEM_DYN>>>(h_ltc, b_gd, b_tau, gleak, cm, out);
}